// round 16
// baseline (speedup 1.0000x reference)
#include <cuda_runtime.h>
#include <cuda_bf16.h>
#include <cuda_fp16.h>
#include <math.h>
#include <stdint.h>

#define BSZ   2
#define SEQ   2048
#define EMB   2048
#define NH    16
#define DH    128
#define QKVN  ((NH + 2) * DH)   // 2304
#define MROWS (BSZ * SEQ)       // 4096
#define GK    2048               // inner K of both GEMMs

// ---------------- scratch (__device__ globals: allocation-free) ------------
__device__ __align__(128) __half g_x16[(size_t)MROWS * EMB];
__device__ __align__(128) __half g_wa16[(size_t)GK * QKVN];    // [K][N] f16
__device__ __align__(128) __half g_wo16[(size_t)GK * EMB];     // [K][N] f16
__device__ __align__(128) __half g_q16[(size_t)MROWS * EMB];   // pre-scaled q
__device__ __align__(128) __half g_a16[(size_t)MROWS * EMB];
__device__ __align__(128) __half g_k16[(size_t)MROWS * DH];
__device__ __align__(128) __half g_v16[(size_t)MROWS * DH];

// ---------------- PTX helpers (sm_80-class only; no 'a' features) ----------
__device__ __forceinline__ uint32_t smem_u32(const void* p) {
    uint32_t a;
    asm("{ .reg .u64 t; cvta.to.shared.u64 t, %1; cvt.u32.u64 %0, t; }"
        : "=r"(a) : "l"(p));
    return a;
}
__device__ __forceinline__ void cp_async16(uint32_t dst, const void* src) {
    asm volatile("cp.async.cg.shared.global [%0], [%1], 16;"
                 :: "r"(dst), "l"(src) : "memory");
}
__device__ __forceinline__ void cp_commit() {
    asm volatile("cp.async.commit_group;" ::: "memory");
}
__device__ __forceinline__ void cp_wait1() {
    asm volatile("cp.async.wait_group 1;" ::: "memory");
}
__device__ __forceinline__ void cp_wait0() {
    asm volatile("cp.async.wait_group 0;" ::: "memory");
}
__device__ __forceinline__ void ldsm4(uint32_t* r, uint32_t addr) {
    asm volatile("ldmatrix.sync.aligned.m8n8.x4.shared.b16 {%0,%1,%2,%3}, [%4];"
                 : "=r"(r[0]), "=r"(r[1]), "=r"(r[2]), "=r"(r[3]) : "r"(addr));
}
__device__ __forceinline__ void ldsm4t(uint32_t* r, uint32_t addr) {
    asm volatile("ldmatrix.sync.aligned.m8n8.x4.trans.shared.b16 {%0,%1,%2,%3}, [%4];"
                 : "=r"(r[0]), "=r"(r[1]), "=r"(r[2]), "=r"(r[3]) : "r"(addr));
}
__device__ __forceinline__ void ldsm2t(uint32_t* r, uint32_t addr) {
    asm volatile("ldmatrix.sync.aligned.m8n8.x2.trans.shared.b16 {%0,%1}, [%2];"
                 : "=r"(r[0]), "=r"(r[1]) : "r"(addr));
}
__device__ __forceinline__ void mma_f16a(float* c, const uint32_t* a,
                                         uint32_t b0, uint32_t b1) {
    asm volatile(
        "mma.sync.aligned.m16n8k16.row.col.f32.f16.f16.f32 "
        "{%0,%1,%2,%3}, {%4,%5,%6,%7}, {%8,%9}, {%0,%1,%2,%3};"
        : "+f"(c[0]), "+f"(c[1]), "+f"(c[2]), "+f"(c[3])
        : "r"(a[0]), "r"(a[1]), "r"(a[2]), "r"(a[3]), "r"(b0), "r"(b1));
}
__device__ __forceinline__ void mma_f16(float* c, uint32_t a0, uint32_t a1,
                                        uint32_t a2, uint32_t a3,
                                        uint32_t b0, uint32_t b1) {
    asm volatile(
        "mma.sync.aligned.m16n8k16.row.col.f32.f16.f16.f32 "
        "{%0,%1,%2,%3}, {%4,%5,%6,%7}, {%8,%9}, {%0,%1,%2,%3};"
        : "+f"(c[0]), "+f"(c[1]), "+f"(c[2]), "+f"(c[3])
        : "r"(a0), "r"(a1), "r"(a2), "r"(a3), "r"(b0), "r"(b1));
}
__device__ __forceinline__ uint32_t ex2_f16x2(float xhi, float xlo) {
    uint32_t h, r;
    asm("cvt.rn.f16x2.f32 %0, %1, %2;" : "=r"(h) : "f"(xhi), "f"(xlo));
    asm("ex2.approx.f16x2 %0, %1;" : "=r"(r) : "r"(h));
    return r;
}
__device__ __forceinline__ float ex2f(float x) {
    float r;
    asm("ex2.approx.f32 %0, %1;" : "=f"(r) : "f"(x));
    return r;
}
__device__ __forceinline__ uint32_t phf2(float x, float y) {
    __half2 t(__float2half_rn(x), __float2half_rn(y));
    return *(uint32_t*)&t;
}

// ---------------------------------------------------------------------------
// fused fp32 -> f16 conversion of x, w_attn, w_out in one launch
// ---------------------------------------------------------------------------
#define N4_X   (MROWS * EMB / 4)        // 2097152
#define N4_WA  (GK * QKVN / 4)          // 1179648
#define N4_WO  (GK * EMB / 4)           // 1048576
#define N4_ALL (N4_X + N4_WA + N4_WO)

__global__ void __launch_bounds__(256) conv_all(const float* __restrict__ x,
                                                const float* __restrict__ wa,
                                                const float* __restrict__ wo,
                                                __half* __restrict__ x16,
                                                __half* __restrict__ wa16,
                                                __half* __restrict__ wo16) {
    int i = blockIdx.x * blockDim.x + threadIdx.x;
    int stride = gridDim.x * blockDim.x;
    for (; i < N4_ALL; i += stride) {
        const float* src;
        __half* dst;
        int j;
        if (i < N4_X) {
            src = x; dst = x16; j = i;
        } else if (i < N4_X + N4_WA) {
            src = wa; dst = wa16; j = i - N4_X;
        } else {
            src = wo; dst = wo16; j = i - N4_X - N4_WA;
        }
        float4 v = ((const float4*)src)[j];
        ((uint32_t*)dst)[2 * j]     = phf2(v.x, v.y);
        ((uint32_t*)dst)[2 * j + 1] = phf2(v.z, v.w);
    }
}

// ---------------------------------------------------------------------------
// Plain f16 GEMM: C[M,N] = A16 @ W16, A [M][K], W [K][N] (native layout).
// CTA 128x128, 8 warps (2x4, warp 64x32), K chunk 32, 3-stage cp.async.
// B fragments via ldmatrix.trans on k-rows. 3 CTAs/SM (occupancy experiment).
// MODE 0: fp32 C out.  MODE 1: fused qkv epilogue -> q16(scaled)/k16/v16.
// ---------------------------------------------------------------------------
#define KCH     32
#define AROW    80
#define BROW    272
#define ATILE   (128 * AROW)           // 10240
#define BTILE   (KCH * BROW)           // 8704
#define OFF_A   0
#define OFF_B   ATILE
#define STAGEB  (ATILE + BTILE)        // 18944
#define GSMEM   (3 * STAGEB)           // 56832

template <int MODE>
__global__ void __launch_bounds__(256, 3)
gemm_mma(const __half* __restrict__ A, const __half* __restrict__ W,
         float* __restrict__ C, __half* __restrict__ q16,
         __half* __restrict__ k16, __half* __restrict__ v16, int N) {
    extern __shared__ char smc[];
    const uint32_t sbase = smem_u32(smc);

    const int tid  = threadIdx.x;
    const int wid  = tid >> 5;
    const int lane = tid & 31;
    const int bm = blockIdx.y * 128;
    const int bn = blockIdx.x * 128;
    const int wm = (wid >> 2) * 64;
    const int wn = (wid & 3) * 32;

    const int r  = tid >> 1;
    const int hf = tid & 1;
    const __half* pA = A + (size_t)(bm + r) * GK + hf * 16;
    const uint32_t adst = (uint32_t)(r * AROW + hf * 32);
    const int brow = tid >> 3;
    const int bseg = tid & 7;
    const __half* pW = W + (size_t)brow * N + bn + bseg * 16;
    const uint32_t bdst = (uint32_t)(brow * BROW + bseg * 32);

    float c[4][4][4];
#pragma unroll
    for (int mt = 0; mt < 4; mt++)
#pragma unroll
        for (int nt = 0; nt < 4; nt++)
#pragma unroll
            for (int k = 0; k < 4; k++) c[mt][nt][k] = 0.0f;

    const int NCH = GK / KCH;   // 64

#pragma unroll
    for (int p = 0; p < 2; p++) {
        const uint32_t st = sbase + p * STAGEB;
        const int k0 = p * KCH;
        cp_async16(st + OFF_A + adst, pA + k0);
        cp_async16(st + OFF_A + adst + 16, pA + k0 + 8);
        cp_async16(st + OFF_B + bdst, pW + (size_t)k0 * N);
        cp_async16(st + OFF_B + bdst + 16, pW + (size_t)k0 * N + 8);
        cp_commit();
    }

    int sidx = 0;
    for (int ch = 0; ch < NCH; ch++) {
        if (ch + 1 < NCH) cp_wait1(); else cp_wait0();
        __syncthreads();
        if (ch + 2 < NCH) {
            int s2 = sidx + 2; if (s2 >= 3) s2 -= 3;
            const uint32_t st2 = sbase + s2 * STAGEB;
            const int k0 = (ch + 2) * KCH;
            cp_async16(st2 + OFF_A + adst, pA + k0);
            cp_async16(st2 + OFF_A + adst + 16, pA + k0 + 8);
            cp_async16(st2 + OFF_B + bdst, pW + (size_t)k0 * N);
            cp_async16(st2 + OFF_B + bdst + 16, pW + (size_t)k0 * N + 8);
            cp_commit();
        }
        const uint32_t st = sbase + sidx * STAGEB;

#pragma unroll
        for (int ks = 0; ks < 2; ks++) {
            const uint32_t kcol = (uint32_t)(ks * 32 + (lane >> 4) * 16);
            uint32_t a[4][4];
#pragma unroll
            for (int mt = 0; mt < 4; mt++) {
                uint32_t ra = st + OFF_A +
                              (uint32_t)((wm + mt * 16 + (lane & 15)) * AROW) + kcol;
                ldsm4(a[mt], ra);
            }
            uint32_t bf0[4], bf1[4];
            uint32_t rb = st + OFF_B +
                          (uint32_t)((ks * 16 + (lane & 15)) * BROW) +
                          (uint32_t)((wn + (lane >> 4) * 8) * 2);
            ldsm4t(bf0, rb);
            ldsm4t(bf1, rb + 32);
#pragma unroll
            for (int mt = 0; mt < 4; mt++) {
                mma_f16a(c[mt][0], a[mt], bf0[0], bf0[1]);
                mma_f16a(c[mt][1], a[mt], bf0[2], bf0[3]);
                mma_f16a(c[mt][2], a[mt], bf1[0], bf1[1]);
                mma_f16a(c[mt][3], a[mt], bf1[2], bf1[3]);
            }
        }
        sidx = (sidx + 1 == 3) ? 0 : sidx + 1;
    }

    // ---- epilogue ----
    if (MODE == 0) {
#pragma unroll
        for (int mt = 0; mt < 4; mt++)
#pragma unroll
            for (int nt = 0; nt < 4; nt++) {
                int row = bm + wm + mt * 16 + (lane >> 2);
                int col = bn + wn + nt * 8 + (lane & 3) * 2;
                *(float2*)&C[(size_t)row * N + col] =
                    make_float2(c[mt][nt][0], c[mt][nt][1]);
                *(float2*)&C[(size_t)(row + 8) * N + col] =
                    make_float2(c[mt][nt][2], c[mt][nt][3]);
            }
    } else {
        const float sc = 0.08838834764831845f * 1.4426950408889634f;
#pragma unroll
        for (int mt = 0; mt < 4; mt++)
#pragma unroll
            for (int nt = 0; nt < 4; nt++) {
                int row = bm + wm + mt * 16 + (lane >> 2);
                int col = bn + wn + nt * 8 + (lane & 3) * 2;
                float v0 = c[mt][nt][0], v1 = c[mt][nt][1];
                float v2 = c[mt][nt][2], v3 = c[mt][nt][3];
                if (bn < EMB) {
                    *(uint32_t*)(q16 + (size_t)row * EMB + col) =
                        phf2(v0 * sc, v1 * sc);
                    *(uint32_t*)(q16 + (size_t)(row + 8) * EMB + col) =
                        phf2(v2 * sc, v3 * sc);
                } else if (bn < EMB + DH) {
                    int lc = col - EMB;
                    *(uint32_t*)(k16 + (size_t)row * DH + lc) = phf2(v0, v1);
                    *(uint32_t*)(k16 + (size_t)(row + 8) * DH + lc) = phf2(v2, v3);
                } else {
                    int lc = col - EMB - DH;
                    *(uint32_t*)(v16 + (size_t)row * DH + lc) = phf2(v0, v1);
                    *(uint32_t*)(v16 + (size_t)(row + 8) * DH + lc) = phf2(v2, v3);
                }
            }
    }
}

// ---------------------------------------------------------------------------
// Tensor-core flash MQA: Q f16 (pre-scaled) x K f16, P f16 x V f16,
// row-sum via ones-column. 2-stage K/V pipeline, 2 CTAs/SM. (unchanged)
// ---------------------------------------------------------------------------
#define FROW    272
#define OFF_Q   0
#define OFF_ST  (128 * FROW)
#define STAGEF  (2 * 64 * FROW)
#define FSMEM   (OFF_ST + 2 * STAGEF)   // 104448

__device__ __forceinline__ void issue_kv_tile(
    uint32_t stbase, int lr, int lcb, size_t ge,
    const __half* __restrict__ k16, const __half* __restrict__ v16) {
    uint32_t d = stbase + (uint32_t)(lr * FROW + lcb);
    const char* pk = (const char*)(k16 + ge);
    const char* pv = (const char*)(v16 + ge);
#pragma unroll
    for (int jj = 0; jj < 4; jj++) {
        cp_async16(d + jj * 16, pk + jj * 16);
        cp_async16(d + 64 * FROW + jj * 16, pv + jj * 16);
    }
}

__global__ void __launch_bounds__(256, 2)
mqa_flash_mma(const __half* __restrict__ gq16,
              const __half* __restrict__ gk16,
              const __half* __restrict__ gv16, __half* __restrict__ a16) {
    extern __shared__ char smf[];
    const uint32_t sb = smem_u32(smf);
    const int tid  = threadIdx.x;
    const int wid  = tid >> 5;
    const int lane = tid & 31;
    const int q0 = blockIdx.x * 128;
    const int h  = blockIdx.y;
    const int b  = blockIdx.z;
    const int wm = wid * 16;

    if (tid < 128) {
        int s = tid >> 6, row = tid & 63;
        char* vrow = smf + OFF_ST + s * STAGEF + 64 * FROW + row * FROW + 256;
        *(uint4*)vrow = make_uint4(0x00003C00u, 0u, 0u, 0u);
    }

    const int lr  = tid >> 2;
    const int lcb = (tid & 3) * 64;
    const size_t gebase = ((size_t)(b * SEQ + lr) << 7) + (lcb >> 1);

    {
        int row = tid >> 1, c0 = (tid & 1) * 64;
        const char* src = (const char*)(gq16 + (size_t)(b * SEQ + q0 + row) * EMB +
                                        h * DH + c0);
        uint32_t dq = sb + OFF_Q + (uint32_t)(row * FROW + c0 * 2);
#pragma unroll
        for (int p = 0; p < 8; p++) cp_async16(dq + p * 16, src + p * 16);
    }
    issue_kv_tile(sb + OFF_ST, lr, lcb, gebase, gk16, gv16);
    cp_commit();
    issue_kv_tile(sb + OFF_ST + STAGEF, lr, lcb, gebase + 64 * 128, gk16, gv16);
    cp_commit();

    float O[17][4];
#pragma unroll
    for (int f = 0; f < 17; f++)
#pragma unroll
        for (int j = 0; j < 4; j++) O[f][j] = 0.0f;
    float m0 = -1e30f, m1 = -1e30f;

    const int NT = SEQ / 64;
    for (int t = 0; t < NT; t++) {
        if (t + 1 < NT) cp_wait1(); else cp_wait0();
        __syncthreads();
        const uint32_t stb = sb + OFF_ST + (t & 1) * STAGEF;

        float c[8][4];
#pragma unroll
        for (int nt = 0; nt < 8; nt++)
#pragma unroll
            for (int j = 0; j < 4; j++) c[nt][j] = 0.0f;

#pragma unroll
        for (int ks = 0; ks < 8; ks++) {
            const uint32_t kcol = (uint32_t)(ks * 32 + (lane >> 4) * 16);
            uint32_t aq[4], kh[4][4];
            ldsm4(aq, sb + OFF_Q + (uint32_t)((wm + (lane & 15)) * FROW) + kcol);
#pragma unroll
            for (int g = 0; g < 4; g++) {
                uint32_t ko = stb + (uint32_t)((g * 16 + (lane & 15)) * FROW) + kcol;
                ldsm4(kh[g], ko);
            }
#pragma unroll
            for (int g = 0; g < 4; g++) {
                mma_f16a(c[2 * g],     aq, kh[g][0], kh[g][2]);
                mma_f16a(c[2 * g + 1], aq, kh[g][1], kh[g][3]);
            }
        }

        float mt0 = -1e30f, mt1 = -1e30f;
#pragma unroll
        for (int nt = 0; nt < 8; nt++) {
            mt0 = fmaxf(mt0, fmaxf(c[nt][0], c[nt][1]));
            mt1 = fmaxf(mt1, fmaxf(c[nt][2], c[nt][3]));
        }
        mt0 = fmaxf(mt0, __shfl_xor_sync(0xffffffffu, mt0, 1));
        mt0 = fmaxf(mt0, __shfl_xor_sync(0xffffffffu, mt0, 2));
        mt1 = fmaxf(mt1, __shfl_xor_sync(0xffffffffu, mt1, 1));
        mt1 = fmaxf(mt1, __shfl_xor_sync(0xffffffffu, mt1, 2));
        float mn0 = fmaxf(m0, mt0), mn1 = fmaxf(m1, mt1);
        float corr0 = ex2f(m0 - mn0), corr1 = ex2f(m1 - mn1);
        m0 = mn0;
        m1 = mn1;
#pragma unroll
        for (int f = 0; f < 17; f++) {
            O[f][0] *= corr0; O[f][1] *= corr0;
            O[f][2] *= corr1; O[f][3] *= corr1;
        }
        uint32_t ph[8][2];
#pragma unroll
        for (int nt = 0; nt < 8; nt++) {
            ph[nt][0] = ex2_f16x2(c[nt][1] - mn0, c[nt][0] - mn0);
            ph[nt][1] = ex2_f16x2(c[nt][3] - mn1, c[nt][2] - mn1);
        }

        const uint32_t vb = stb + 64 * FROW;
#pragma unroll
        for (int j = 0; j < 4; j++) {
            uint32_t a0 = ph[2 * j][0], a1 = ph[2 * j][1];
            uint32_t a2 = ph[2 * j + 1][0], a3 = ph[2 * j + 1][1];
            uint32_t vrow = vb + (uint32_t)((j * 16 + (lane & 15)) * FROW);
            const uint32_t ccol = (uint32_t)((lane >> 4) * 8) * 2;
            uint32_t vfa[4][4];
#pragma unroll
            for (int g = 0; g < 4; g++) ldsm4t(vfa[g], vrow + g * 32 + ccol);
#pragma unroll
            for (int g = 0; g < 4; g++) {
                mma_f16(O[2 * g],     a0, a1, a2, a3, vfa[g][0], vfa[g][1]);
                mma_f16(O[2 * g + 1], a0, a1, a2, a3, vfa[g][2], vfa[g][3]);
            }
#pragma unroll
            for (int g = 0; g < 4; g++) ldsm4t(vfa[g], vrow + 128 + g * 32 + ccol);
#pragma unroll
            for (int g = 0; g < 4; g++) {
                mma_f16(O[8 + 2 * g],     a0, a1, a2, a3, vfa[g][0], vfa[g][1]);
                mma_f16(O[8 + 2 * g + 1], a0, a1, a2, a3, vfa[g][2], vfa[g][3]);
            }
            uint32_t lh[2];
            ldsm2t(lh, vrow + 256);
            mma_f16(O[16], a0, a1, a2, a3, lh[0], lh[1]);
        }

        __syncthreads();
        if (t + 2 < NT) {
            issue_kv_tile(stb, lr, lcb, gebase + (size_t)(t + 2) * 64 * 128,
                          gk16, gv16);
            cp_commit();
        }
    }

    float l0 = __shfl_sync(0xffffffffu, O[16][0], lane & 28);
    float l1 = __shfl_sync(0xffffffffu, O[16][2], lane & 28);
    float inv0 = 1.0f / l0, inv1 = 1.0f / l1;
    size_t base0 = (size_t)(b * SEQ + q0 + wm + (lane >> 2)) * EMB + h * DH +
                   2 * (lane & 3);
    size_t base1 = base0 + (size_t)8 * EMB;
#pragma unroll
    for (int nt = 0; nt < 16; nt++) {
        *(uint32_t*)(a16 + base0 + nt * 8) = phf2(O[nt][0] * inv0, O[nt][1] * inv0);
        *(uint32_t*)(a16 + base1 + nt * 8) = phf2(O[nt][2] * inv1, O[nt][3] * inv1);
    }
}

// ---------------------------------------------------------------------------
extern "C" void kernel_launch(void* const* d_in, const int* in_sizes, int n_in,
                              void* d_out, int out_size) {
    const float* x      = (const float*)d_in[0];
    const float* w_attn = (const float*)d_in[1];
    const float* w_out  = (const float*)d_in[2];
    float* out = (float*)d_out;

    __half *x16, *wa16, *wo16, *q16, *a16, *k16, *v16;
    cudaGetSymbolAddress((void**)&x16, g_x16);
    cudaGetSymbolAddress((void**)&wa16, g_wa16);
    cudaGetSymbolAddress((void**)&wo16, g_wo16);
    cudaGetSymbolAddress((void**)&q16, g_q16);
    cudaGetSymbolAddress((void**)&a16, g_a16);
    cudaGetSymbolAddress((void**)&k16, g_k16);
    cudaGetSymbolAddress((void**)&v16, g_v16);

    cudaFuncSetAttribute(gemm_mma<0>, cudaFuncAttributeMaxDynamicSharedMemorySize,
                         GSMEM);
    cudaFuncSetAttribute(gemm_mma<1>, cudaFuncAttributeMaxDynamicSharedMemorySize,
                         GSMEM);
    cudaFuncSetAttribute(mqa_flash_mma, cudaFuncAttributeMaxDynamicSharedMemorySize,
                         FSMEM);

    // 1) fused conversion of all inputs (one launch)
    conv_all<<<1184, 256>>>(x, w_attn, w_out, x16, wa16, wo16);

    // 2) qkv = x @ w_attn with fused q-scale/k16/v16 epilogue
    gemm_mma<1><<<dim3(QKVN / 128, MROWS / 128), 256, GSMEM>>>(
        x16, wa16, nullptr, q16, k16, v16, QKVN);

    // 3) tensor-core flash MQA -> f16 attn (2 CTAs/SM)
    mqa_flash_mma<<<dim3(SEQ / 128, NH, BSZ), 256, FSMEM>>>(
        q16, k16, v16, a16);

    // 4) out = attn @ w_out
    gemm_mma<0><<<dim3(EMB / 128, MROWS / 128), 256, GSMEM>>>(
        a16, wo16, out, nullptr, nullptr, nullptr, EMB);
}

// round 17
// speedup vs baseline: 1.2988x; 1.2988x over previous
#include <cuda_runtime.h>
#include <cuda_bf16.h>
#include <cuda_fp16.h>
#include <math.h>
#include <stdint.h>

#define BSZ   2
#define SEQ   2048
#define EMB   2048
#define NH    16
#define DH    128
#define QKVN  ((NH + 2) * DH)   // 2304
#define MROWS (BSZ * SEQ)       // 4096
#define GK    2048               // inner K of both GEMMs

// ---------------- scratch (__device__ globals: allocation-free) ------------
__device__ __align__(128) __half g_x16[(size_t)MROWS * EMB];
__device__ __align__(128) __half g_wa16[(size_t)GK * QKVN];    // [K][N] f16
__device__ __align__(128) __half g_wo16[(size_t)GK * EMB];     // [K][N] f16
__device__ __align__(128) __half g_q16[(size_t)MROWS * EMB];   // pre-scaled q
__device__ __align__(128) __half g_a16[(size_t)MROWS * EMB];
__device__ __align__(128) __half g_k16[(size_t)MROWS * DH];
__device__ __align__(128) __half g_v16[(size_t)MROWS * DH];

// ---------------- PTX helpers (sm_80-class only; no 'a' features) ----------
__device__ __forceinline__ uint32_t smem_u32(const void* p) {
    uint32_t a;
    asm("{ .reg .u64 t; cvta.to.shared.u64 t, %1; cvt.u32.u64 %0, t; }"
        : "=r"(a) : "l"(p));
    return a;
}
__device__ __forceinline__ void cp_async16(uint32_t dst, const void* src) {
    asm volatile("cp.async.cg.shared.global [%0], [%1], 16;"
                 :: "r"(dst), "l"(src) : "memory");
}
__device__ __forceinline__ void cp_commit() {
    asm volatile("cp.async.commit_group;" ::: "memory");
}
__device__ __forceinline__ void cp_wait1() {
    asm volatile("cp.async.wait_group 1;" ::: "memory");
}
__device__ __forceinline__ void cp_wait0() {
    asm volatile("cp.async.wait_group 0;" ::: "memory");
}
__device__ __forceinline__ void ldsm4(uint32_t* r, uint32_t addr) {
    asm volatile("ldmatrix.sync.aligned.m8n8.x4.shared.b16 {%0,%1,%2,%3}, [%4];"
                 : "=r"(r[0]), "=r"(r[1]), "=r"(r[2]), "=r"(r[3]) : "r"(addr));
}
__device__ __forceinline__ void ldsm4t(uint32_t* r, uint32_t addr) {
    asm volatile("ldmatrix.sync.aligned.m8n8.x4.trans.shared.b16 {%0,%1,%2,%3}, [%4];"
                 : "=r"(r[0]), "=r"(r[1]), "=r"(r[2]), "=r"(r[3]) : "r"(addr));
}
__device__ __forceinline__ void ldsm2t(uint32_t* r, uint32_t addr) {
    asm volatile("ldmatrix.sync.aligned.m8n8.x2.trans.shared.b16 {%0,%1}, [%2];"
                 : "=r"(r[0]), "=r"(r[1]) : "r"(addr));
}
__device__ __forceinline__ void mma_f16a(float* c, const uint32_t* a,
                                         uint32_t b0, uint32_t b1) {
    asm volatile(
        "mma.sync.aligned.m16n8k16.row.col.f32.f16.f16.f32 "
        "{%0,%1,%2,%3}, {%4,%5,%6,%7}, {%8,%9}, {%0,%1,%2,%3};"
        : "+f"(c[0]), "+f"(c[1]), "+f"(c[2]), "+f"(c[3])
        : "r"(a[0]), "r"(a[1]), "r"(a[2]), "r"(a[3]), "r"(b0), "r"(b1));
}
__device__ __forceinline__ void mma_f16(float* c, uint32_t a0, uint32_t a1,
                                        uint32_t a2, uint32_t a3,
                                        uint32_t b0, uint32_t b1) {
    asm volatile(
        "mma.sync.aligned.m16n8k16.row.col.f32.f16.f16.f32 "
        "{%0,%1,%2,%3}, {%4,%5,%6,%7}, {%8,%9}, {%0,%1,%2,%3};"
        : "+f"(c[0]), "+f"(c[1]), "+f"(c[2]), "+f"(c[3])
        : "r"(a0), "r"(a1), "r"(a2), "r"(a3), "r"(b0), "r"(b1));
}
__device__ __forceinline__ uint32_t ex2_f16x2(float xhi, float xlo) {
    uint32_t h, r;
    asm("cvt.rn.f16x2.f32 %0, %1, %2;" : "=r"(h) : "f"(xhi), "f"(xlo));
    asm("ex2.approx.f16x2 %0, %1;" : "=r"(r) : "r"(h));
    return r;
}
__device__ __forceinline__ float ex2f(float x) {
    float r;
    asm("ex2.approx.f32 %0, %1;" : "=f"(r) : "f"(x));
    return r;
}
__device__ __forceinline__ uint32_t phf2(float x, float y) {
    __half2 t(__float2half_rn(x), __float2half_rn(y));
    return *(uint32_t*)&t;
}

// ---------------------------------------------------------------------------
// fused fp32 -> f16 conversion of x, w_attn, w_out in one launch
// ---------------------------------------------------------------------------
#define N4_X   (MROWS * EMB / 4)
#define N4_WA  (GK * QKVN / 4)
#define N4_WO  (GK * EMB / 4)
#define N4_ALL (N4_X + N4_WA + N4_WO)

__global__ void __launch_bounds__(256) conv_all(const float* __restrict__ x,
                                                const float* __restrict__ wa,
                                                const float* __restrict__ wo,
                                                __half* __restrict__ x16,
                                                __half* __restrict__ wa16,
                                                __half* __restrict__ wo16) {
    int i = blockIdx.x * blockDim.x + threadIdx.x;
    int stride = gridDim.x * blockDim.x;
    for (; i < N4_ALL; i += stride) {
        const float* src;
        __half* dst;
        int j;
        if (i < N4_X) {
            src = x; dst = x16; j = i;
        } else if (i < N4_X + N4_WA) {
            src = wa; dst = wa16; j = i - N4_X;
        } else {
            src = wo; dst = wo16; j = i - N4_X - N4_WA;
        }
        float4 v = ((const float4*)src)[j];
        ((uint32_t*)dst)[2 * j]     = phf2(v.x, v.y);
        ((uint32_t*)dst)[2 * j + 1] = phf2(v.z, v.w);
    }
}

// ---------------------------------------------------------------------------
// Plain f16 GEMM: C[M,N] = A16 @ W16, A [M][K], W [K][N] (native layout).
// CTA 128x128, 8 warps (2x4, warp 64x32), K chunk 32, 3-stage cp.async.
// B fragments via ldmatrix.trans on k-rows. 2 CTAs/SM (R15 config).
// MODE 0: fp32 C out.  MODE 1: fused qkv epilogue -> q16(scaled)/k16/v16.
// ---------------------------------------------------------------------------
#define KCH     32
#define AROW    80
#define BROW    272
#define ATILE   (128 * AROW)           // 10240
#define BTILE   (KCH * BROW)           // 8704
#define OFF_A   0
#define OFF_B   ATILE
#define STAGEB  (ATILE + BTILE)        // 18944
#define GSMEM   (3 * STAGEB)           // 56832

template <int MODE>
__global__ void __launch_bounds__(256)
gemm_mma(const __half* __restrict__ A, const __half* __restrict__ W,
         float* __restrict__ C, __half* __restrict__ q16,
         __half* __restrict__ k16, __half* __restrict__ v16, int N) {
    extern __shared__ char smc[];
    const uint32_t sbase = smem_u32(smc);

    const int tid  = threadIdx.x;
    const int wid  = tid >> 5;
    const int lane = tid & 31;
    const int bm = blockIdx.y * 128;
    const int bn = blockIdx.x * 128;
    const int wm = (wid >> 2) * 64;
    const int wn = (wid & 3) * 32;

    const int r  = tid >> 1;
    const int hf = tid & 1;
    const __half* pA = A + (size_t)(bm + r) * GK + hf * 16;
    const uint32_t adst = (uint32_t)(r * AROW + hf * 32);
    const int brow = tid >> 3;
    const int bseg = tid & 7;
    const __half* pW = W + (size_t)brow * N + bn + bseg * 16;
    const uint32_t bdst = (uint32_t)(brow * BROW + bseg * 32);

    float c[4][4][4];
#pragma unroll
    for (int mt = 0; mt < 4; mt++)
#pragma unroll
        for (int nt = 0; nt < 4; nt++)
#pragma unroll
            for (int k = 0; k < 4; k++) c[mt][nt][k] = 0.0f;

    const int NCH = GK / KCH;   // 64

#pragma unroll
    for (int p = 0; p < 2; p++) {
        const uint32_t st = sbase + p * STAGEB;
        const int k0 = p * KCH;
        cp_async16(st + OFF_A + adst, pA + k0);
        cp_async16(st + OFF_A + adst + 16, pA + k0 + 8);
        cp_async16(st + OFF_B + bdst, pW + (size_t)k0 * N);
        cp_async16(st + OFF_B + bdst + 16, pW + (size_t)k0 * N + 8);
        cp_commit();
    }

    int sidx = 0;
    for (int ch = 0; ch < NCH; ch++) {
        if (ch + 1 < NCH) cp_wait1(); else cp_wait0();
        __syncthreads();
        if (ch + 2 < NCH) {
            int s2 = sidx + 2; if (s2 >= 3) s2 -= 3;
            const uint32_t st2 = sbase + s2 * STAGEB;
            const int k0 = (ch + 2) * KCH;
            cp_async16(st2 + OFF_A + adst, pA + k0);
            cp_async16(st2 + OFF_A + adst + 16, pA + k0 + 8);
            cp_async16(st2 + OFF_B + bdst, pW + (size_t)k0 * N);
            cp_async16(st2 + OFF_B + bdst + 16, pW + (size_t)k0 * N + 8);
            cp_commit();
        }
        const uint32_t st = sbase + sidx * STAGEB;

#pragma unroll
        for (int ks = 0; ks < 2; ks++) {
            const uint32_t kcol = (uint32_t)(ks * 32 + (lane >> 4) * 16);
            uint32_t a[4][4];
#pragma unroll
            for (int mt = 0; mt < 4; mt++) {
                uint32_t ra = st + OFF_A +
                              (uint32_t)((wm + mt * 16 + (lane & 15)) * AROW) + kcol;
                ldsm4(a[mt], ra);
            }
            uint32_t bf0[4], bf1[4];
            uint32_t rb = st + OFF_B +
                          (uint32_t)((ks * 16 + (lane & 15)) * BROW) +
                          (uint32_t)((wn + (lane >> 4) * 8) * 2);
            ldsm4t(bf0, rb);
            ldsm4t(bf1, rb + 32);
#pragma unroll
            for (int mt = 0; mt < 4; mt++) {
                mma_f16a(c[mt][0], a[mt], bf0[0], bf0[1]);
                mma_f16a(c[mt][1], a[mt], bf0[2], bf0[3]);
                mma_f16a(c[mt][2], a[mt], bf1[0], bf1[1]);
                mma_f16a(c[mt][3], a[mt], bf1[2], bf1[3]);
            }
        }
        sidx = (sidx + 1 == 3) ? 0 : sidx + 1;
    }

    // ---- epilogue ----
    if (MODE == 0) {
#pragma unroll
        for (int mt = 0; mt < 4; mt++)
#pragma unroll
            for (int nt = 0; nt < 4; nt++) {
                int row = bm + wm + mt * 16 + (lane >> 2);
                int col = bn + wn + nt * 8 + (lane & 3) * 2;
                *(float2*)&C[(size_t)row * N + col] =
                    make_float2(c[mt][nt][0], c[mt][nt][1]);
                *(float2*)&C[(size_t)(row + 8) * N + col] =
                    make_float2(c[mt][nt][2], c[mt][nt][3]);
            }
    } else {
        const float sc = 0.08838834764831845f * 1.4426950408889634f;
#pragma unroll
        for (int mt = 0; mt < 4; mt++)
#pragma unroll
            for (int nt = 0; nt < 4; nt++) {
                int row = bm + wm + mt * 16 + (lane >> 2);
                int col = bn + wn + nt * 8 + (lane & 3) * 2;
                float v0 = c[mt][nt][0], v1 = c[mt][nt][1];
                float v2 = c[mt][nt][2], v3 = c[mt][nt][3];
                if (bn < EMB) {
                    *(uint32_t*)(q16 + (size_t)row * EMB + col) =
                        phf2(v0 * sc, v1 * sc);
                    *(uint32_t*)(q16 + (size_t)(row + 8) * EMB + col) =
                        phf2(v2 * sc, v3 * sc);
                } else if (bn < EMB + DH) {
                    int lc = col - EMB;
                    *(uint32_t*)(k16 + (size_t)row * DH + lc) = phf2(v0, v1);
                    *(uint32_t*)(k16 + (size_t)(row + 8) * DH + lc) = phf2(v2, v3);
                } else {
                    int lc = col - EMB - DH;
                    *(uint32_t*)(v16 + (size_t)row * DH + lc) = phf2(v0, v1);
                    *(uint32_t*)(v16 + (size_t)(row + 8) * DH + lc) = phf2(v2, v3);
                }
            }
    }
}

// ---------------------------------------------------------------------------
// Tensor-core flash MQA: Q f16 (pre-scaled) x K f16, P f16 x V f16,
// row-sum via ones-column. 2-stage K/V pipeline, 2 CTAs/SM.
// ---------------------------------------------------------------------------
#define FROW    272
#define OFF_Q   0
#define OFF_ST  (128 * FROW)
#define STAGEF  (2 * 64 * FROW)
#define FSMEM   (OFF_ST + 2 * STAGEF)   // 104448

__device__ __forceinline__ void issue_kv_tile(
    uint32_t stbase, int lr, int lcb, size_t ge,
    const __half* __restrict__ k16, const __half* __restrict__ v16) {
    uint32_t d = stbase + (uint32_t)(lr * FROW + lcb);
    const char* pk = (const char*)(k16 + ge);
    const char* pv = (const char*)(v16 + ge);
#pragma unroll
    for (int jj = 0; jj < 4; jj++) {
        cp_async16(d + jj * 16, pk + jj * 16);
        cp_async16(d + 64 * FROW + jj * 16, pv + jj * 16);
    }
}

__global__ void __launch_bounds__(256, 2)
mqa_flash_mma(const __half* __restrict__ gq16,
              const __half* __restrict__ gk16,
              const __half* __restrict__ gv16, __half* __restrict__ a16) {
    extern __shared__ char smf[];
    const uint32_t sb = smem_u32(smf);
    const int tid  = threadIdx.x;
    const int wid  = tid >> 5;
    const int lane = tid & 31;
    const int q0 = blockIdx.x * 128;
    const int h  = blockIdx.y;
    const int b  = blockIdx.z;
    const int wm = wid * 16;

    if (tid < 128) {
        int s = tid >> 6, row = tid & 63;
        char* vrow = smf + OFF_ST + s * STAGEF + 64 * FROW + row * FROW + 256;
        *(uint4*)vrow = make_uint4(0x00003C00u, 0u, 0u, 0u);
    }

    const int lr  = tid >> 2;
    const int lcb = (tid & 3) * 64;
    const size_t gebase = ((size_t)(b * SEQ + lr) << 7) + (lcb >> 1);

    {
        int row = tid >> 1, c0 = (tid & 1) * 64;
        const char* src = (const char*)(gq16 + (size_t)(b * SEQ + q0 + row) * EMB +
                                        h * DH + c0);
        uint32_t dq = sb + OFF_Q + (uint32_t)(row * FROW + c0 * 2);
#pragma unroll
        for (int p = 0; p < 8; p++) cp_async16(dq + p * 16, src + p * 16);
    }
    issue_kv_tile(sb + OFF_ST, lr, lcb, gebase, gk16, gv16);
    cp_commit();
    issue_kv_tile(sb + OFF_ST + STAGEF, lr, lcb, gebase + 64 * 128, gk16, gv16);
    cp_commit();

    float O[17][4];
#pragma unroll
    for (int f = 0; f < 17; f++)
#pragma unroll
        for (int j = 0; j < 4; j++) O[f][j] = 0.0f;
    float m0 = -1e30f, m1 = -1e30f;

    const int NT = SEQ / 64;
    for (int t = 0; t < NT; t++) {
        if (t + 1 < NT) cp_wait1(); else cp_wait0();
        __syncthreads();
        const uint32_t stb = sb + OFF_ST + (t & 1) * STAGEF;

        float c[8][4];
#pragma unroll
        for (int nt = 0; nt < 8; nt++)
#pragma unroll
            for (int j = 0; j < 4; j++) c[nt][j] = 0.0f;

#pragma unroll
        for (int ks = 0; ks < 8; ks++) {
            const uint32_t kcol = (uint32_t)(ks * 32 + (lane >> 4) * 16);
            uint32_t aq[4], kh[4][4];
            ldsm4(aq, sb + OFF_Q + (uint32_t)((wm + (lane & 15)) * FROW) + kcol);
#pragma unroll
            for (int g = 0; g < 4; g++) {
                uint32_t ko = stb + (uint32_t)((g * 16 + (lane & 15)) * FROW) + kcol;
                ldsm4(kh[g], ko);
            }
#pragma unroll
            for (int g = 0; g < 4; g++) {
                mma_f16a(c[2 * g],     aq, kh[g][0], kh[g][2]);
                mma_f16a(c[2 * g + 1], aq, kh[g][1], kh[g][3]);
            }
        }

        float mt0 = -1e30f, mt1 = -1e30f;
#pragma unroll
        for (int nt = 0; nt < 8; nt++) {
            mt0 = fmaxf(mt0, fmaxf(c[nt][0], c[nt][1]));
            mt1 = fmaxf(mt1, fmaxf(c[nt][2], c[nt][3]));
        }
        mt0 = fmaxf(mt0, __shfl_xor_sync(0xffffffffu, mt0, 1));
        mt0 = fmaxf(mt0, __shfl_xor_sync(0xffffffffu, mt0, 2));
        mt1 = fmaxf(mt1, __shfl_xor_sync(0xffffffffu, mt1, 1));
        mt1 = fmaxf(mt1, __shfl_xor_sync(0xffffffffu, mt1, 2));
        float mn0 = fmaxf(m0, mt0), mn1 = fmaxf(m1, mt1);
        float corr0 = ex2f(m0 - mn0), corr1 = ex2f(m1 - mn1);
        m0 = mn0;
        m1 = mn1;
#pragma unroll
        for (int f = 0; f < 17; f++) {
            O[f][0] *= corr0; O[f][1] *= corr0;
            O[f][2] *= corr1; O[f][3] *= corr1;
        }
        uint32_t ph[8][2];
#pragma unroll
        for (int nt = 0; nt < 8; nt++) {
            ph[nt][0] = ex2_f16x2(c[nt][1] - mn0, c[nt][0] - mn0);
            ph[nt][1] = ex2_f16x2(c[nt][3] - mn1, c[nt][2] - mn1);
        }

        const uint32_t vb = stb + 64 * FROW;
#pragma unroll
        for (int j = 0; j < 4; j++) {
            uint32_t a0 = ph[2 * j][0], a1 = ph[2 * j][1];
            uint32_t a2 = ph[2 * j + 1][0], a3 = ph[2 * j + 1][1];
            uint32_t vrow = vb + (uint32_t)((j * 16 + (lane & 15)) * FROW);
            const uint32_t ccol = (uint32_t)((lane >> 4) * 8) * 2;
            uint32_t vfa[4][4];
#pragma unroll
            for (int g = 0; g < 4; g++) ldsm4t(vfa[g], vrow + g * 32 + ccol);
#pragma unroll
            for (int g = 0; g < 4; g++) {
                mma_f16(O[2 * g],     a0, a1, a2, a3, vfa[g][0], vfa[g][1]);
                mma_f16(O[2 * g + 1], a0, a1, a2, a3, vfa[g][2], vfa[g][3]);
            }
#pragma unroll
            for (int g = 0; g < 4; g++) ldsm4t(vfa[g], vrow + 128 + g * 32 + ccol);
#pragma unroll
            for (int g = 0; g < 4; g++) {
                mma_f16(O[8 + 2 * g],     a0, a1, a2, a3, vfa[g][0], vfa[g][1]);
                mma_f16(O[8 + 2 * g + 1], a0, a1, a2, a3, vfa[g][2], vfa[g][3]);
            }
            uint32_t lh[2];
            ldsm2t(lh, vrow + 256);
            mma_f16(O[16], a0, a1, a2, a3, lh[0], lh[1]);
        }

        __syncthreads();
        if (t + 2 < NT) {
            issue_kv_tile(stb, lr, lcb, gebase + (size_t)(t + 2) * 64 * 128,
                          gk16, gv16);
            cp_commit();
        }
    }

    float l0 = __shfl_sync(0xffffffffu, O[16][0], lane & 28);
    float l1 = __shfl_sync(0xffffffffu, O[16][2], lane & 28);
    float inv0 = 1.0f / l0, inv1 = 1.0f / l1;
    size_t base0 = (size_t)(b * SEQ + q0 + wm + (lane >> 2)) * EMB + h * DH +
                   2 * (lane & 3);
    size_t base1 = base0 + (size_t)8 * EMB;
#pragma unroll
    for (int nt = 0; nt < 16; nt++) {
        *(uint32_t*)(a16 + base0 + nt * 8) = phf2(O[nt][0] * inv0, O[nt][1] * inv0);
        *(uint32_t*)(a16 + base1 + nt * 8) = phf2(O[nt][2] * inv1, O[nt][3] * inv1);
    }
}

// ---------------------------------------------------------------------------
extern "C" void kernel_launch(void* const* d_in, const int* in_sizes, int n_in,
                              void* d_out, int out_size) {
    const float* x      = (const float*)d_in[0];
    const float* w_attn = (const float*)d_in[1];
    const float* w_out  = (const float*)d_in[2];
    float* out = (float*)d_out;

    __half *x16, *wa16, *wo16, *q16, *a16, *k16, *v16;
    cudaGetSymbolAddress((void**)&x16, g_x16);
    cudaGetSymbolAddress((void**)&wa16, g_wa16);
    cudaGetSymbolAddress((void**)&wo16, g_wo16);
    cudaGetSymbolAddress((void**)&q16, g_q16);
    cudaGetSymbolAddress((void**)&a16, g_a16);
    cudaGetSymbolAddress((void**)&k16, g_k16);
    cudaGetSymbolAddress((void**)&v16, g_v16);

    cudaFuncSetAttribute(gemm_mma<0>, cudaFuncAttributeMaxDynamicSharedMemorySize,
                         GSMEM);
    cudaFuncSetAttribute(gemm_mma<1>, cudaFuncAttributeMaxDynamicSharedMemorySize,
                         GSMEM);
    cudaFuncSetAttribute(mqa_flash_mma, cudaFuncAttributeMaxDynamicSharedMemorySize,
                         FSMEM);

    // 1) fused conversion of all inputs (one launch)
    conv_all<<<1184, 256>>>(x, w_attn, w_out, x16, wa16, wo16);

    // 2) qkv = x @ w_attn with fused q-scale/k16/v16 epilogue
    gemm_mma<1><<<dim3(QKVN / 128, MROWS / 128), 256, GSMEM>>>(
        x16, wa16, nullptr, q16, k16, v16, QKVN);

    // 3) tensor-core flash MQA -> f16 attn (2 CTAs/SM)
    mqa_flash_mma<<<dim3(SEQ / 128, NH, BSZ), 256, FSMEM>>>(
        q16, k16, v16, a16);

    // 4) out = attn @ w_out
    gemm_mma<0><<<dim3(EMB / 128, MROWS / 128), 256, GSMEM>>>(
        a16, wo16, out, nullptr, nullptr, nullptr, EMB);
}